// round 4
// baseline (speedup 1.0000x reference)
#include <cuda_runtime.h>

#define BB 4
#define G 8
#define DD 8
#define HH 256
#define WW 320
#define NN 9
#define HW (HH*WW)

// Fused MLP constants: [0,128) W0*a0, [128,144) bias0, [144,272) W1*a1,
// [272,280) bias1, [280,288) W2, [288] b2
__device__ float g_fused[289];
// Interleaved scratch: per (b,h,w) cell of 16 floats = {xn(d0),s(d0),...,xn(d7),s(d7)}
__device__ float4 g_scratch[BB * HW * 4];

__global__ void prep_kernel(const float* __restrict__ w0, const float* __restrict__ g0,
                            const float* __restrict__ b0, const float* __restrict__ m0,
                            const float* __restrict__ v0, const float* __restrict__ w1,
                            const float* __restrict__ g1, const float* __restrict__ b1,
                            const float* __restrict__ m1, const float* __restrict__ v1,
                            const float* __restrict__ w2, const float* __restrict__ b2) {
    int t = threadIdx.x;
    if (t < 16) {
        float a = g0[t] * rsqrtf(v0[t] + 1e-5f);
        #pragma unroll
        for (int g = 0; g < 8; ++g) g_fused[t * 8 + g] = w0[t * 8 + g] * a;
        g_fused[128 + t] = b0[t] - m0[t] * a;
    }
    if (t < 8) {
        float a = g1[t] * rsqrtf(v1[t] + 1e-5f);
        #pragma unroll
        for (int c = 0; c < 16; ++c) g_fused[144 + t * 16 + c] = w1[t * 16 + c] * a;
        g_fused[272 + t] = b1[t] - m1[t] * a;
        g_fused[280 + t] = w2[t];
    }
    if (t == 0) g_fused[288] = b2[0];
}

// One thread per (b,h,w): compute s (MLP over G) and xnorm for all 8 depths,
// store interleaved for vectorized sampling.
__global__ __launch_bounds__(256) void mlp_kernel(const float* __restrict__ cost,
                                                  const float* __restrict__ ds,
                                                  const float* __restrict__ dmin,
                                                  const float* __restrict__ dmax) {
    __shared__ float sw[289];
    int tid = blockIdx.x * 256 + threadIdx.x;
    for (int i = threadIdx.x; i < 289; i += 256) sw[i] = g_fused[i];
    __syncthreads();

    int b = tid / HW;
    int p = tid % HW;
    float inv_min = 1.f / __ldg(dmin + b);
    float inv_max = 1.f / __ldg(dmax + b);
    float inv_range = 1.f / (inv_min - inv_max);

    const float* costb = cost + (size_t)b * G * DD * HW + p;
    const float* dsb   = ds + (size_t)b * DD * HW + p;

    #pragma unroll
    for (int dp = 0; dp < 4; ++dp) {
        int d0 = dp * 2;
        float xA[8], xB[8];
        #pragma unroll
        for (int g = 0; g < 8; ++g) {
            xA[g] = costb[(size_t)(g * DD + d0) * HW];
            xB[g] = costb[(size_t)(g * DD + d0 + 1) * HW];
        }
        float h0A[16], h0B[16];
        #pragma unroll
        for (int o = 0; o < 16; ++o) {
            float aA = sw[128 + o], aB = aA;
            #pragma unroll
            for (int g = 0; g < 8; ++g) {
                float wv = sw[o * 8 + g];
                aA = fmaf(wv, xA[g], aA);
                aB = fmaf(wv, xB[g], aB);
            }
            h0A[o] = fmaxf(aA, 0.f);
            h0B[o] = fmaxf(aB, 0.f);
        }
        float sA = sw[288], sB = sA;
        #pragma unroll
        for (int o = 0; o < 8; ++o) {
            float aA = sw[272 + o], aB = aA;
            #pragma unroll
            for (int c = 0; c < 16; ++c) {
                float wv = sw[144 + o * 16 + c];
                aA = fmaf(wv, h0A[c], aA);
                aB = fmaf(wv, h0B[c], aB);
            }
            float w2v = sw[280 + o];
            sA = fmaf(w2v, fmaxf(aA, 0.f), sA);
            sB = fmaf(w2v, fmaxf(aB, 0.f), sB);
        }
        float xnA = (1.f / dsb[(size_t)d0 * HW] - inv_max) * inv_range;
        float xnB = (1.f / dsb[(size_t)(d0 + 1) * HW] - inv_max) * inv_range;
        g_scratch[(size_t)tid * 4 + dp] = make_float4(xnA, sA, xnB, sB);
    }
}

// One thread per (b,h,w): 9 neighbors, bilinear sample of (xnorm, s) for all 8 d,
// sigmoid depth-kernel, weighted accumulation.
__global__ __launch_bounds__(256) void agg_kernel(const float* __restrict__ grid,
                                                  const float* __restrict__ fwt,
                                                  float* __restrict__ out) {
    int tid = blockIdx.x * 256 + threadIdx.x;
    int b = tid / HW;
    int p = tid % HW;
    int h = p / WW;
    int w = p % WW;

    // center xnorm for all 8 d
    float xn[8];
    {
        const float4* cc = g_scratch + (size_t)tid * 4;
        #pragma unroll
        for (int j = 0; j < 4; ++j) {
            float4 v = cc[j];
            xn[2 * j] = v.x;
            xn[2 * j + 1] = v.z;
        }
    }
    float acc[8];
    #pragma unroll
    for (int d = 0; d < 8; ++d) acc[d] = 0.f;

    const float LOG2E2 = 2.885390082f;   // 2*log2(e)
    const float BIAS   = -5.770780164f;  // -4*log2(e)

    #pragma unroll
    for (int n = 0; n < NN; ++n) {
        float2 g2 = ((const float2*)grid)[(size_t)(b * NN * HH + n * HH + h) * WW + w];
        float fx = fminf(fmaxf((g2.x + 1.f) * (0.5f * WW) - 0.5f, 0.f), (float)(WW - 1));
        float fy = fminf(fmaxf((g2.y + 1.f) * (0.5f * HH) - 0.5f, 0.f), (float)(HH - 1));
        float x0f = floorf(fx), y0f = floorf(fy);
        float wx = fx - x0f, wy = fy - y0f;
        int x0 = (int)x0f, y0 = (int)y0f;
        int x1 = min(x0 + 1, WW - 1), y1 = min(y0 + 1, HH - 1);
        float w00 = (1.f - wx) * (1.f - wy);
        float w01 = wx * (1.f - wy);
        float w10 = (1.f - wx) * wy;
        float w11 = wx * wy;
        float f = fwt[(size_t)((b * NN + n) * HH + h) * WW + w];

        const float4* p00 = g_scratch + (size_t)(b * HW + y0 * WW + x0) * 4;
        const float4* p01 = g_scratch + (size_t)(b * HW + y0 * WW + x1) * 4;
        const float4* p10 = g_scratch + (size_t)(b * HW + y1 * WW + x0) * 4;
        const float4* p11 = g_scratch + (size_t)(b * HW + y1 * WW + x1) * 4;

        #pragma unroll
        for (int j = 0; j < 4; ++j) {
            float4 a = p00[j], c1 = p01[j], c2 = p10[j], c3 = p11[j];
            float xs0 = w00 * a.x + w01 * c1.x + w10 * c2.x + w11 * c3.x;
            float ss0 = w00 * a.y + w01 * c1.y + w10 * c2.y + w11 * c3.y;
            float xs1 = w00 * a.z + w01 * c1.z + w10 * c2.z + w11 * c3.z;
            float ss1 = w00 * a.w + w01 * c1.w + w10 * c2.w + w11 * c3.w;
            int d0 = 2 * j;
            float diff0 = fminf(fabsf(xs0 - xn[d0]) * 40.f, 4.f);
            float diff1 = fminf(fabsf(xs1 - xn[d0 + 1]) * 40.f, 4.f);
            // sigmoid(4 - 2*diff) = 1/(1+exp2(diff*2log2e - 4log2e))
            float dw0 = 1.f / (1.f + exp2f(fmaf(diff0, LOG2E2, BIAS)));
            float dw1 = 1.f / (1.f + exp2f(fmaf(diff1, LOG2E2, BIAS)));
            acc[d0]     = fmaf(ss0 * f, dw0, acc[d0]);
            acc[d0 + 1] = fmaf(ss1 * f, dw1, acc[d0 + 1]);
        }
    }

    #pragma unroll
    for (int d = 0; d < 8; ++d)
        out[(size_t)(b * DD + d) * HW + p] = acc[d];
}

extern "C" void kernel_launch(void* const* d_in, const int* in_sizes, int n_in,
                              void* d_out, int out_size) {
    const float* cost = (const float*)d_in[0];
    const float* ds   = (const float*)d_in[1];
    const float* dmin = (const float*)d_in[2];
    const float* dmax = (const float*)d_in[3];
    const float* grid = (const float*)d_in[4];
    const float* fwt  = (const float*)d_in[5];

    prep_kernel<<<1, 32>>>((const float*)d_in[6], (const float*)d_in[7],
                           (const float*)d_in[8], (const float*)d_in[9],
                           (const float*)d_in[10], (const float*)d_in[11],
                           (const float*)d_in[12], (const float*)d_in[13],
                           (const float*)d_in[14], (const float*)d_in[15],
                           (const float*)d_in[16], (const float*)d_in[17]);

    int total = BB * HW;              // 327680 = 1280 * 256 exactly
    mlp_kernel<<<total / 256, 256>>>(cost, ds, dmin, dmax);
    agg_kernel<<<total / 256, 256>>>(grid, fwt, (float*)d_out);
}

// round 6
// speedup vs baseline: 1.2680x; 1.2680x over previous
#include <cuda_runtime.h>

#define BB 4
#define G 8
#define DD 8
#define HH 256
#define WW 320
#define NN 9
#define HW (HH*WW)

// Interleaved scratch: per (b,h,w) cell of 16 floats = {xn(d0),s(d0),...,xn(d7),s(d7)}
__device__ float4 g_scratch[BB * HW * 4];

// One thread per (b,h,w): compute s (MLP over G) and xnorm for all 8 depths.
// Fused BN weights computed per block into shared (no separate prep launch).
// Shared float layout: [0,128) w0*a0, [128,144) bias0, [144,272) w1*a1,
// [272,280) bias1, [280,288) w2, [288] b2
__global__ __launch_bounds__(256) void mlp_kernel(
    const float* __restrict__ cost, const float* __restrict__ ds,
    const float* __restrict__ dmin, const float* __restrict__ dmax,
    const float* __restrict__ w0, const float* __restrict__ g0,
    const float* __restrict__ b0, const float* __restrict__ m0,
    const float* __restrict__ v0, const float* __restrict__ w1,
    const float* __restrict__ g1, const float* __restrict__ b1,
    const float* __restrict__ m1, const float* __restrict__ v1,
    const float* __restrict__ w2, const float* __restrict__ b2)
{
    __shared__ __align__(16) float sw[292];
    float4* sw4 = (float4*)sw;
    int t = threadIdx.x;
    if (t < 16) {
        float a = g0[t] * rsqrtf(v0[t] + 1e-5f);
        #pragma unroll
        for (int g = 0; g < 8; ++g) sw[t * 8 + g] = w0[t * 8 + g] * a;
        sw[128 + t] = b0[t] - m0[t] * a;
    } else if (t >= 32 && t < 40) {
        int o = t - 32;
        float a = g1[o] * rsqrtf(v1[o] + 1e-5f);
        #pragma unroll
        for (int c = 0; c < 16; ++c) sw[144 + o * 16 + c] = w1[o * 16 + c] * a;
        sw[272 + o] = b1[o] - m1[o] * a;
        sw[280 + o] = w2[o];
    } else if (t == 64) {
        sw[288] = b2[0];
    }
    __syncthreads();

    int tid = blockIdx.x * 256 + threadIdx.x;
    int b = tid / HW;
    int p = tid % HW;
    float inv_min = 1.f / __ldg(dmin + b);
    float inv_max = 1.f / __ldg(dmax + b);
    float inv_range = 1.f / (inv_min - inv_max);

    const float* costb = cost + (size_t)b * G * DD * HW + p;
    const float* dsb   = ds + (size_t)b * DD * HW + p;

    #pragma unroll
    for (int dp = 0; dp < 4; ++dp) {
        int d0 = dp * 2;
        float xA[8], xB[8];
        #pragma unroll
        for (int g = 0; g < 8; ++g) {
            xA[g] = costb[(size_t)(g * DD + d0) * HW];
            xB[g] = costb[(size_t)(g * DD + d0 + 1) * HW];
        }
        float h0A[16], h0B[16];
        #pragma unroll
        for (int o = 0; o < 16; ++o) {
            float4 wa = sw4[o * 2];        // w0[o][0..3]
            float4 wb = sw4[o * 2 + 1];    // w0[o][4..7]
            float bias = sw[128 + o];
            float aA = bias, aB = bias;
            aA = fmaf(wa.x, xA[0], aA); aB = fmaf(wa.x, xB[0], aB);
            aA = fmaf(wa.y, xA[1], aA); aB = fmaf(wa.y, xB[1], aB);
            aA = fmaf(wa.z, xA[2], aA); aB = fmaf(wa.z, xB[2], aB);
            aA = fmaf(wa.w, xA[3], aA); aB = fmaf(wa.w, xB[3], aB);
            aA = fmaf(wb.x, xA[4], aA); aB = fmaf(wb.x, xB[4], aB);
            aA = fmaf(wb.y, xA[5], aA); aB = fmaf(wb.y, xB[5], aB);
            aA = fmaf(wb.z, xA[6], aA); aB = fmaf(wb.z, xB[6], aB);
            aA = fmaf(wb.w, xA[7], aA); aB = fmaf(wb.w, xB[7], aB);
            h0A[o] = fmaxf(aA, 0.f);
            h0B[o] = fmaxf(aB, 0.f);
        }
        float sA = sw[288], sB = sA;
        #pragma unroll
        for (int o = 0; o < 8; ++o) {
            float aA = sw[272 + o], aB = aA;
            #pragma unroll
            for (int k = 0; k < 4; ++k) {
                float4 wv = sw4[36 + o * 4 + k];   // w1[o][4k..4k+3]
                int c = k * 4;
                aA = fmaf(wv.x, h0A[c],     aA); aB = fmaf(wv.x, h0B[c],     aB);
                aA = fmaf(wv.y, h0A[c + 1], aA); aB = fmaf(wv.y, h0B[c + 1], aB);
                aA = fmaf(wv.z, h0A[c + 2], aA); aB = fmaf(wv.z, h0B[c + 2], aB);
                aA = fmaf(wv.w, h0A[c + 3], aA); aB = fmaf(wv.w, h0B[c + 3], aB);
            }
            float w2v = sw[280 + o];
            sA = fmaf(w2v, fmaxf(aA, 0.f), sA);
            sB = fmaf(w2v, fmaxf(aB, 0.f), sB);
        }
        float xnA = (1.f / dsb[(size_t)d0 * HW] - inv_max) * inv_range;
        float xnB = (1.f / dsb[(size_t)(d0 + 1) * HW] - inv_max) * inv_range;
        g_scratch[(size_t)tid * 4 + dp] = make_float4(xnA, sA, xnB, sB);
    }
}

// 4 threads per pixel: thread (pix, j) owns depth-pair {2j, 2j+1}.
// Each corner gather is one LDG.128 with contiguous warp addressing (4 wavefronts).
__global__ __launch_bounds__(256) void agg_kernel(const float* __restrict__ grid,
                                                  const float* __restrict__ fwt,
                                                  float* __restrict__ out) {
    int tid = blockIdx.x * 256 + threadIdx.x;
    int pix = tid >> 2;
    int j = tid & 3;
    int b = pix / HW;
    int p = pix % HW;
    int h = p / WW;
    int w = p % WW;

    float4 c = g_scratch[(size_t)pix * 4 + j];
    float xn0 = c.x, xn1 = c.z;
    float acc0 = 0.f, acc1 = 0.f;

    const float4* base = g_scratch + (size_t)b * HW * 4 + j;
    const float LOG2E2 = 2.885390082f;   // 2*log2(e)
    const float BIAS   = -5.770780164f;  // -4*log2(e)

    #pragma unroll
    for (int n = 0; n < NN; ++n) {
        float2 g2 = ((const float2*)grid)[(size_t)(b * NN * HH + n * HH + h) * WW + w];
        float fx = fminf(fmaxf((g2.x + 1.f) * (0.5f * WW) - 0.5f, 0.f), (float)(WW - 1));
        float fy = fminf(fmaxf((g2.y + 1.f) * (0.5f * HH) - 0.5f, 0.f), (float)(HH - 1));
        float x0f = floorf(fx), y0f = floorf(fy);
        float wx = fx - x0f, wy = fy - y0f;
        int x0 = (int)x0f, y0 = (int)y0f;
        int x1 = min(x0 + 1, WW - 1), y1 = min(y0 + 1, HH - 1);
        float w00 = (1.f - wx) * (1.f - wy);
        float w01 = wx * (1.f - wy);
        float w10 = (1.f - wx) * wy;
        float w11 = wx * wy;
        float f = fwt[(size_t)((b * NN + n) * HH + h) * WW + w];

        float4 a0 = base[(size_t)(y0 * WW + x0) * 4];
        float4 a1 = base[(size_t)(y0 * WW + x1) * 4];
        float4 a2 = base[(size_t)(y1 * WW + x0) * 4];
        float4 a3 = base[(size_t)(y1 * WW + x1) * 4];

        float xs0 = w00 * a0.x + w01 * a1.x + w10 * a2.x + w11 * a3.x;
        float ss0 = w00 * a0.y + w01 * a1.y + w10 * a2.y + w11 * a3.y;
        float xs1 = w00 * a0.z + w01 * a1.z + w10 * a2.z + w11 * a3.z;
        float ss1 = w00 * a0.w + w01 * a1.w + w10 * a2.w + w11 * a3.w;

        float diff0 = fminf(fabsf(xs0 - xn0) * 40.f, 4.f);
        float diff1 = fminf(fabsf(xs1 - xn1) * 40.f, 4.f);
        float dw0 = 1.f / (1.f + exp2f(fmaf(diff0, LOG2E2, BIAS)));
        float dw1 = 1.f / (1.f + exp2f(fmaf(diff1, LOG2E2, BIAS)));
        acc0 = fmaf(ss0 * f, dw0, acc0);
        acc1 = fmaf(ss1 * f, dw1, acc1);
    }

    out[(size_t)(b * DD + 2 * j) * HW + p]     = acc0;
    out[(size_t)(b * DD + 2 * j + 1) * HW + p] = acc1;
}

extern "C" void kernel_launch(void* const* d_in, const int* in_sizes, int n_in,
                              void* d_out, int out_size) {
    const float* cost = (const float*)d_in[0];
    const float* ds   = (const float*)d_in[1];
    const float* dmin = (const float*)d_in[2];
    const float* dmax = (const float*)d_in[3];
    const float* grid = (const float*)d_in[4];
    const float* fwt  = (const float*)d_in[5];

    int total = BB * HW;                    // 327680 pixels
    mlp_kernel<<<total / 256, 256>>>(cost, ds, dmin, dmax,
                                     (const float*)d_in[6], (const float*)d_in[7],
                                     (const float*)d_in[8], (const float*)d_in[9],
                                     (const float*)d_in[10], (const float*)d_in[11],
                                     (const float*)d_in[12], (const float*)d_in[13],
                                     (const float*)d_in[14], (const float*)d_in[15],
                                     (const float*)d_in[16], (const float*)d_in[17]);
    agg_kernel<<<total * 4 / 256, 256>>>(grid, fwt, (float*)d_out);
}